// round 8
// baseline (speedup 1.0000x reference)
#include <cuda_runtime.h>
#include <cstdint>
#include <cstddef>

#define L_SEQ 32768
#define DIM   512
#define DIM4  2048
#define NCTA  32          // recurrence CTAs
#define GCTA  116         // GEMM CTAs (total grid = 148)
#define NBLK  256         // row-blocks of 128 rows
#define NTIL  4096        // 256 row-blocks x 16 col-tiles

// Scratch (static device globals: allocation-free per harness rules)
__device__ float g_xp[(size_t)L_SEQ * DIM4];      // 256 MB x-projection
__device__ unsigned long long g_hx[2][DIM];       // tagged hidden: (tag<<32)|bits
__device__ int g_cnt[NBLK];                       // per-row-block completed tiles

// ---------------------------------------------------------------------------
// Phase 0: reset state each launch (graph-replay safe)
// ---------------------------------------------------------------------------
__global__ void init_state(const float* __restrict__ h0) {
    int tid = threadIdx.x;
    if (tid < NBLK) g_cnt[tid] = 0;
    if (tid < DIM) {
        g_hx[0][tid] = (unsigned long long)__float_as_uint(h0[tid]);  // tag 0
        g_hx[1][tid] = 0xFFFFFFFF00000000ull;                         // tag ~0
    }
}

struct GemmSmem { float As[16][132]; float Bs[16][128]; };   // 16.6 KB
struct RecSmem  { float hsh[2][DIM]; float xpsh[2][64]; };   //  4.6 KB

// ---------------------------------------------------------------------------
// Fused kernel: CTAs 0..31 run the sequential LSTM; CTAs 32..147 run the
// x-projection GEMM persistently, publishing row-block readiness via g_cnt.
// ---------------------------------------------------------------------------
__global__ __launch_bounds__(512, 1) void lstm_fused(
    const float* __restrict__ xs, const float* __restrict__ Wi,
    const float* __restrict__ bias, const float* __restrict__ Wh,
    const float* __restrict__ c0, float* __restrict__ out)
{
    __shared__ __align__(16) unsigned char s_raw[sizeof(GemmSmem)];
    const int tid = threadIdx.x;
    const int blk = blockIdx.x;

    // =================== GEMM path (CTAs 32..147) ===================
    if (blk >= NCTA) {
        GemmSmem& S = *reinterpret_cast<GemmSmem*>(s_raw);
        const int tx = tid & 31;   // n: 4 cols each
        const int ty = tid >> 5;   // m: 8 rows each

        for (int idx = blk - NCTA; idx < NTIL; idx += GCTA) {
            const int bm = (idx >> 4) * 128;   // row-major tile order
            const int bn = (idx & 15) * 128;

            float acc[8][4];
#pragma unroll
            for (int i = 0; i < 8; i++)
#pragma unroll
                for (int j = 0; j < 4; j++) acc[i][j] = 0.f;

            for (int k0 = 0; k0 < DIM; k0 += 16) {
                {   // A tile 128x16, transposed into As[k][m]
                    int row = tid >> 2;
                    int c4  = (tid & 3) << 2;
                    float4 v = *(const float4*)(xs + (size_t)(bm + row) * DIM + k0 + c4);
                    S.As[c4 + 0][row] = v.x;
                    S.As[c4 + 1][row] = v.y;
                    S.As[c4 + 2][row] = v.z;
                    S.As[c4 + 3][row] = v.w;
                }
                {   // B tile 16x128
                    int row = tid >> 5;
                    int c4  = (tid & 31) << 2;
                    *(float4*)(&S.Bs[row][c4]) =
                        *(const float4*)(Wi + (size_t)(k0 + row) * DIM4 + bn + c4);
                }
                __syncthreads();
#pragma unroll
                for (int kk = 0; kk < 16; kk++) {
                    float a[8], bb[4];
                    *(float4*)(a)     = *(const float4*)(&S.As[kk][ty * 8]);
                    *(float4*)(a + 4) = *(const float4*)(&S.As[kk][ty * 8 + 4]);
                    *(float4*)(bb)    = *(const float4*)(&S.Bs[kk][tx * 4]);
#pragma unroll
                    for (int i = 0; i < 8; i++)
#pragma unroll
                        for (int j = 0; j < 4; j++)
                            acc[i][j] = fmaf(a[i], bb[j], acc[i][j]);
                }
                __syncthreads();
            }

            float4 bv = *(const float4*)(bias + bn + tx * 4);
#pragma unroll
            for (int i = 0; i < 8; i++) {
                float4 o;
                o.x = acc[i][0] + bv.x;
                o.y = acc[i][1] + bv.y;
                o.z = acc[i][2] + bv.z;
                o.w = acc[i][3] + bv.w;
                *(float4*)(g_xp + (size_t)(bm + ty * 8 + i) * DIM4 + bn + tx * 4) = o;
            }
            __threadfence();
            __syncthreads();
            if (tid == 0) atomicAdd(&g_cnt[idx >> 4], 1);
        }
        return;
    }

    // =================== Recurrence path (CTAs 0..31) ===================
    RecSmem& R = *reinterpret_cast<RecSmem*>(s_raw);
    const int w = tid >> 5;        // warp 0..15 -> local d
    const int l = tid & 31;
    const int d = blk * 16 + w;
    const int g = l >> 3;          // lane-group -> gate (0:i 1:f 2:g 3:o)

    // Register-resident weights: lane l covers k = 4l + 128m + j (m<4, j<4)
    float wreg[4][4][4];
#pragma unroll
    for (int q = 0; q < 4; q++)
#pragma unroll
        for (int m = 0; m < 4; m++)
#pragma unroll
            for (int j = 0; j < 4; j++)
                wreg[q][m][j] = __ldg(Wh + (size_t)(4 * l + 128 * m + j) * DIM4 + q * DIM + d);

    float cst = __ldg(c0 + d);

    const float escale = (g == 2) ? -2.0f : -1.0f;
    const float pa     = (g == 2) ?  2.0f :  1.0f;
    const float pb     = (g == 2) ? -1.0f :  0.0f;

    const float* xp_base = g_xp + (tid >> 4) * DIM + blk * 16 + (tid & 15);
    const unsigned FULL = 0xffffffffu;

    // Prologue: ensure rows 0..1 ready, then prefetch xp[0], xp[1]
    int rdy = 0;   // row-blocks confirmed complete (tid0 only)
    if (tid == 0) {
        while (rdy < 1) {
            int c;
            asm volatile("ld.acquire.gpu.global.b32 %0, [%1];"
                         : "=r"(c) : "l"(g_cnt + rdy));
            if (c == 16) rdy++;
        }
    }
    __syncthreads();

    float xv0 = 0.f, xv1 = 0.f;
    if (tid < 64) {
        xv0 = __ldcs(xp_base);
        xv1 = __ldcs(xp_base + DIM4);
    }

    for (int t = 0; t < L_SEQ; t++) {
        const int pbuf = t & 1;

        // Stage x_proj[t] (register, prefetched >=1 full step earlier)
        if (tid < 64) R.xpsh[pbuf][tid] = xv0;

        // tid0: guarantee row-block of step t+2 is GEMM-complete (rare wait)
        if (tid == 0) {
            int need = ((t + 2) >> 7) + 1;
            if (need > NBLK) need = NBLK;
            while (rdy < need) {
                int c;
                asm volatile("ld.acquire.gpu.global.b32 %0, [%1];"
                             : "=r"(c) : "l"(g_cnt + rdy));
                if (c == 16) rdy++;
            }
        }

        // Poll own tagged h element until tag == t (2-way unrolled: two
        // independent in-flight loads halve the sampling period)
        {
            const unsigned long long* hp = &g_hx[pbuf][tid];
            const unsigned want = (unsigned)t;
            unsigned long long v1, v2;
            for (;;) {
                asm volatile("ld.relaxed.gpu.global.b64 %0, [%1];"
                             : "=l"(v1) : "l"(hp));
                asm volatile("ld.relaxed.gpu.global.b64 %0, [%1];"
                             : "=l"(v2) : "l"(hp));
                if ((unsigned)(v1 >> 32) == want) break;
                if ((unsigned)(v2 >> 32) == want) { v1 = v2; break; }
            }
            R.hsh[pbuf][tid] = __uint_as_float((unsigned)v1);
        }
        __syncthreads();

        // Rotate prefetch registers; issue load for t+2 (covered ~1 full step)
        if (tid < 64) {
            xv0 = xv1;
            if (t + 2 < L_SEQ)
                xv1 = __ldcs(xp_base + (size_t)(t + 2) * DIM4);
        }

        // 64 FMAs via 4 LDS.128 (conflict-free), 2 accumulators per gate
        float sA0 = 0.f, sA1 = 0.f, sA2 = 0.f, sA3 = 0.f;
        float sB0 = 0.f, sB1 = 0.f, sB2 = 0.f, sB3 = 0.f;
#pragma unroll
        for (int m = 0; m < 4; m++) {
            float4 hv = *(const float4*)(&R.hsh[pbuf][4 * l + 128 * m]);
            sA0 = fmaf(hv.x, wreg[0][m][0], fmaf(hv.y, wreg[0][m][1], sA0));
            sB0 = fmaf(hv.z, wreg[0][m][2], fmaf(hv.w, wreg[0][m][3], sB0));
            sA1 = fmaf(hv.x, wreg[1][m][0], fmaf(hv.y, wreg[1][m][1], sA1));
            sB1 = fmaf(hv.z, wreg[1][m][2], fmaf(hv.w, wreg[1][m][3], sB1));
            sA2 = fmaf(hv.x, wreg[2][m][0], fmaf(hv.y, wreg[2][m][1], sA2));
            sB2 = fmaf(hv.z, wreg[2][m][2], fmaf(hv.w, wreg[2][m][3], sB2));
            sA3 = fmaf(hv.x, wreg[3][m][0], fmaf(hv.y, wreg[3][m][1], sA3));
            sB3 = fmaf(hv.z, wreg[3][m][2], fmaf(hv.w, wreg[3][m][3], sB3));
        }
        float s0 = sA0 + sB0;
        float s1 = sA1 + sB1;
        float s2 = sA2 + sB2;
        float s3 = sA3 + sB3;

        // Merged butterfly reduce: 4 sums over 32 lanes, ~9 shfls;
        // lane-group g ends holding gate-g total.
        float t0 = __shfl_xor_sync(FULL, s0, 16);
        float t2 = __shfl_xor_sync(FULL, s2, 16);
        float av = (l < 16) ? (s0 + t0) : (s2 + t2);
        float t1 = __shfl_xor_sync(FULL, s1, 16);
        float t3 = __shfl_xor_sync(FULL, s3, 16);
        float bv = (l < 16) ? (s1 + t1) : (s3 + t3);
        float a8 = __shfl_xor_sync(FULL, av, 8);
        float b8 = __shfl_xor_sync(FULL, bv, 8);
        float cc = ((l & 8) == 0) ? (av + a8) : (bv + b8);
        cc += __shfl_xor_sync(FULL, cc, 4);
        cc += __shfl_xor_sync(FULL, cc, 2);
        cc += __shfl_xor_sync(FULL, cc, 1);

        // Activation (branchless per lane-group)
        float y   = cc + R.xpsh[pbuf][g * 16 + w];
        float e   = __expf(escale * y);
        float r   = __fdividef(1.0f, 1.0f + e);
        float act = fmaf(pa, r, pb);   // sigmoid(y) or tanh(y)

        float vi = __shfl_sync(FULL, act, 0);
        float vf = __shfl_sync(FULL, act, 8);
        float vg = __shfl_sync(FULL, act, 16);
        float vo = __shfl_sync(FULL, act, 24);

        cst = fmaf(vf, cst, vi * vg);
        float ca = fminf(fmaxf(cst, -40.f), 40.f);
        float e2 = __expf(-2.0f * ca);
        float th = fmaf(2.0f, __fdividef(1.0f, 1.0f + e2), -1.0f);
        float hn = vo * th;

        if (l == 0) {
            unsigned long long pk =
                ((unsigned long long)(unsigned)(t + 1) << 32) |
                (unsigned long long)__float_as_uint(hn);
            asm volatile("st.relaxed.gpu.global.b64 [%0], %1;"
                         :: "l"(&g_hx[(t + 1) & 1][d]), "l"(pk) : "memory");
        } else if (l == 1) {
            __stcs(out + (size_t)t * DIM + d, hn);
        }
        // no trailing barrier: hsh/xpsh double-buffered
    }
}

// ---------------------------------------------------------------------------
extern "C" void kernel_launch(void* const* d_in, const int* in_sizes, int n_in,
                              void* d_out, int out_size)
{
    const float* xs = (const float*)d_in[0];   // [L, 512]
    const float* Wi = (const float*)d_in[1];   // [512, 2048]
    const float* Wh = (const float*)d_in[2];   // [512, 2048]
    const float* b  = (const float*)d_in[3];   // [2048]
    const float* c0 = (const float*)d_in[4];   // [512]
    const float* h0 = (const float*)d_in[5];   // [512]
    float* out = (float*)d_out;                // [L, 512]

    init_state<<<1, 512>>>(h0);
    lstm_fused<<<NCTA + GCTA, 512>>>(xs, Wi, b, Wh, c0, out);
}

// round 10
// speedup vs baseline: 1.1788x; 1.1788x over previous
#include <cuda_runtime.h>
#include <cstdint>
#include <cstddef>

#define L_SEQ 32768
#define DIM   512
#define DIM4  2048
#define NCTA  32          // recurrence CTAs
#define GCTA  116         // GEMM CTAs (total grid = 148)
#define NBLK  256         // row-blocks of 128 rows
#define NTIL  4096        // 256 row-blocks x 16 col-tiles

// Scratch (static device globals: allocation-free per harness rules)
__device__ float g_xp[(size_t)L_SEQ * DIM4];      // 256 MB x-projection
__device__ unsigned long long g_hx[2][DIM];       // tagged hidden: (tag<<32)|bits
__device__ int g_cnt[NBLK];                       // per-row-block completed tiles

// ---------------------------------------------------------------------------
// Phase 0: reset state each launch (graph-replay safe)
// ---------------------------------------------------------------------------
__global__ void init_state(const float* __restrict__ h0) {
    int tid = threadIdx.x;
    if (tid < NBLK) g_cnt[tid] = 0;
    if (tid < DIM) {
        g_hx[0][tid] = (unsigned long long)__float_as_uint(h0[tid]);  // tag 0
        g_hx[1][tid] = 0xFFFFFFFF00000000ull;                         // tag ~0
    }
}

struct GemmSmem { float As[16][132]; float Bs[16][128]; };   // 16.6 KB
struct RecSmem  { float hsh[2][DIM]; float xpsh[2][64]; };   //  4.6 KB

// ---------------------------------------------------------------------------
// Fused kernel: CTAs 0..31 run the sequential LSTM; CTAs 32..147 run the
// x-projection GEMM persistently, publishing row-block readiness via g_cnt.
// ---------------------------------------------------------------------------
__global__ __launch_bounds__(512, 1) void lstm_fused(
    const float* __restrict__ xs, const float* __restrict__ Wi,
    const float* __restrict__ bias, const float* __restrict__ Wh,
    const float* __restrict__ c0, float* __restrict__ out)
{
    __shared__ __align__(16) unsigned char s_raw[sizeof(GemmSmem)];
    const int tid = threadIdx.x;
    const int blk = blockIdx.x;

    // =================== GEMM path (CTAs 32..147) ===================
    if (blk >= NCTA) {
        GemmSmem& S = *reinterpret_cast<GemmSmem*>(s_raw);
        const int tx = tid & 31;   // n: 4 cols each
        const int ty = tid >> 5;   // m: 8 rows each

        for (int idx = blk - NCTA; idx < NTIL; idx += GCTA) {
            const int bm = (idx >> 4) * 128;   // row-major tile order
            const int bn = (idx & 15) * 128;

            float acc[8][4];
#pragma unroll
            for (int i = 0; i < 8; i++)
#pragma unroll
                for (int j = 0; j < 4; j++) acc[i][j] = 0.f;

            for (int k0 = 0; k0 < DIM; k0 += 16) {
                {   // A tile 128x16, transposed into As[k][m]
                    int row = tid >> 2;
                    int c4  = (tid & 3) << 2;
                    float4 v = *(const float4*)(xs + (size_t)(bm + row) * DIM + k0 + c4);
                    S.As[c4 + 0][row] = v.x;
                    S.As[c4 + 1][row] = v.y;
                    S.As[c4 + 2][row] = v.z;
                    S.As[c4 + 3][row] = v.w;
                }
                {   // B tile 16x128
                    int row = tid >> 5;
                    int c4  = (tid & 31) << 2;
                    *(float4*)(&S.Bs[row][c4]) =
                        *(const float4*)(Wi + (size_t)(k0 + row) * DIM4 + bn + c4);
                }
                __syncthreads();
#pragma unroll
                for (int kk = 0; kk < 16; kk++) {
                    float a[8], bb[4];
                    *(float4*)(a)     = *(const float4*)(&S.As[kk][ty * 8]);
                    *(float4*)(a + 4) = *(const float4*)(&S.As[kk][ty * 8 + 4]);
                    *(float4*)(bb)    = *(const float4*)(&S.Bs[kk][tx * 4]);
#pragma unroll
                    for (int i = 0; i < 8; i++)
#pragma unroll
                        for (int j = 0; j < 4; j++)
                            acc[i][j] = fmaf(a[i], bb[j], acc[i][j]);
                }
                __syncthreads();
            }

            float4 bv = *(const float4*)(bias + bn + tx * 4);
#pragma unroll
            for (int i = 0; i < 8; i++) {
                float4 o;
                o.x = acc[i][0] + bv.x;
                o.y = acc[i][1] + bv.y;
                o.z = acc[i][2] + bv.z;
                o.w = acc[i][3] + bv.w;
                *(float4*)(g_xp + (size_t)(bm + ty * 8 + i) * DIM4 + bn + tx * 4) = o;
            }
            __threadfence();
            __syncthreads();
            if (tid == 0) atomicAdd(&g_cnt[idx >> 4], 1);
        }
        return;
    }

    // =================== Recurrence path (CTAs 0..31) ===================
    RecSmem& R = *reinterpret_cast<RecSmem*>(s_raw);
    const int w = tid >> 5;        // warp 0..15 -> local d
    const int l = tid & 31;
    const int d = blk * 16 + w;
    const int g = l >> 3;          // lane-group -> gate (0:i 1:f 2:g 3:o)

    // Register-resident weights: lane l covers k = 2l + 64m + j (m<8, j<2)
    float wreg[4][8][2];
#pragma unroll
    for (int q = 0; q < 4; q++)
#pragma unroll
        for (int m = 0; m < 8; m++)
#pragma unroll
            for (int j = 0; j < 2; j++)
                wreg[q][m][j] = __ldg(Wh + (size_t)(2 * l + 64 * m + j) * DIM4 + q * DIM + d);

    float cst = __ldg(c0 + d);

    const float escale = (g == 2) ? -2.0f : -1.0f;
    const float pa     = (g == 2) ?  2.0f :  1.0f;
    const float pb     = (g == 2) ? -1.0f :  0.0f;

    const float* xp_base = g_xp + (tid >> 4) * DIM + blk * 16 + (tid & 15);
    const unsigned FULL = 0xffffffffu;

    int rdy = 0;   // row-blocks confirmed complete (tid0 only)
    if (tid == 0) {
        while (rdy < 1) {
            int c;
            asm volatile("ld.acquire.gpu.global.b32 %0, [%1];"
                         : "=r"(c) : "l"(g_cnt + rdy));
            if (c == 16) rdy++;
        }
    }
    __syncthreads();

    // xv prefetched ONE STEP AHEAD (issued during step t-1's compute window)
    float xv = (tid < 64) ? __ldcs(xp_base) : 0.f;

    for (int t = 0; t < L_SEQ; t++) {
        const int pbuf = t & 1;

        // ---- Phase-staggered dual-chain poll of own tagged h element ----
        // Chain A samples at its natural ~latency period; chain B is offset
        // ~250cy behind via an opaque dependent-ALU delay, so the two chains
        // interleave and halve the effective sampling period.
        {
            const unsigned long long* hp = &g_hx[pbuf][tid];
            const unsigned want = (unsigned)t;
            unsigned long long va, vb, v;
            asm volatile("ld.relaxed.gpu.global.b64 %0, [%1];"
                         : "=l"(va) : "l"(hp));
            // ~220cy opaque delay (48 dependent IMADs + shfl identity)
            unsigned dly = tid | 1u;
#pragma unroll
            for (int i = 0; i < 48; i++)
                asm volatile("mad.lo.u32 %0, %0, 3, 1;" : "+r"(dly));
            unsigned zr = __shfl_sync(FULL, dly, l) ^ dly;   // == 0, opaque
            const unsigned long long* hpb =
                (const unsigned long long*)((const char*)hp + zr);
            asm volatile("ld.relaxed.gpu.global.b64 %0, [%1];"
                         : "=l"(vb) : "l"(hpb));
            for (;;) {
                if ((unsigned)(va >> 32) == want) { v = va; break; }
                asm volatile("ld.relaxed.gpu.global.b64 %0, [%1];"
                             : "=l"(va) : "l"(hp));
                if ((unsigned)(vb >> 32) == want) { v = vb; break; }
                asm volatile("ld.relaxed.gpu.global.b64 %0, [%1];"
                             : "=l"(vb) : "l"(hpb));
            }
            R.hsh[pbuf][tid] = __uint_as_float((unsigned)v);
        }
        // tid0: guarantee row-block of step t+1 is GEMM-complete
        // (polls L2 only when `need` crosses a 128-step boundary)
        if (tid == 0) {
            int need = ((t + 1) >> 7) + 1;
            if (need > NBLK) need = NBLK;
            while (rdy < need) {
                int c;
                asm volatile("ld.acquire.gpu.global.b32 %0, [%1];"
                             : "=r"(c) : "l"(g_cnt + rdy));
                if (c == 16) rdy++;
            }
        }
        if (tid < 64) R.xpsh[pbuf][tid] = xv;
        __syncthreads();

        // Prefetch x_proj[t+1] now — covered by a full step's critical path
        if (tid < 64 && t + 1 < L_SEQ)
            xv = __ldcs(xp_base + (size_t)(t + 1) * DIM4);

        // 64 FMAs via 8 float2 LDS (conflict-free)
        float s0 = 0.f, s1 = 0.f, s2 = 0.f, s3 = 0.f;
#pragma unroll
        for (int m = 0; m < 8; m++) {
            float2 hv = *(const float2*)(&R.hsh[pbuf][2 * l + 64 * m]);
            s0 = fmaf(hv.x, wreg[0][m][0], fmaf(hv.y, wreg[0][m][1], s0));
            s1 = fmaf(hv.x, wreg[1][m][0], fmaf(hv.y, wreg[1][m][1], s1));
            s2 = fmaf(hv.x, wreg[2][m][0], fmaf(hv.y, wreg[2][m][1], s2));
            s3 = fmaf(hv.x, wreg[3][m][0], fmaf(hv.y, wreg[3][m][1], s3));
        }

        // Merged butterfly reduce: 4 sums over 32 lanes, ~9 shfls;
        // lane-group g ends holding gate-g total.
        float t0 = __shfl_xor_sync(FULL, s0, 16);
        float t2 = __shfl_xor_sync(FULL, s2, 16);
        float av = (l < 16) ? (s0 + t0) : (s2 + t2);
        float t1 = __shfl_xor_sync(FULL, s1, 16);
        float t3 = __shfl_xor_sync(FULL, s3, 16);
        float bv = (l < 16) ? (s1 + t1) : (s3 + t3);
        float a8 = __shfl_xor_sync(FULL, av, 8);
        float b8 = __shfl_xor_sync(FULL, bv, 8);
        float cc = ((l & 8) == 0) ? (av + a8) : (bv + b8);
        cc += __shfl_xor_sync(FULL, cc, 4);
        cc += __shfl_xor_sync(FULL, cc, 2);
        cc += __shfl_xor_sync(FULL, cc, 1);

        // Activation (branchless per lane-group)
        float y   = cc + R.xpsh[pbuf][g * 16 + w];
        float e   = __expf(escale * y);
        float r   = __fdividef(1.0f, 1.0f + e);
        float act = fmaf(pa, r, pb);   // sigmoid(y) or tanh(y)

        float vi = __shfl_sync(FULL, act, 0);
        float vf = __shfl_sync(FULL, act, 8);
        float vg = __shfl_sync(FULL, act, 16);
        float vo = __shfl_sync(FULL, act, 24);

        cst = fmaf(vf, cst, vi * vg);
        float ca = fminf(fmaxf(cst, -40.f), 40.f);
        float e2 = __expf(-2.0f * ca);
        float th = fmaf(2.0f, __fdividef(1.0f, 1.0f + e2), -1.0f);
        float hn = vo * th;

        if (l == 0) {
            unsigned long long pk =
                ((unsigned long long)(unsigned)(t + 1) << 32) |
                (unsigned long long)__float_as_uint(hn);
            asm volatile("st.relaxed.gpu.global.b64 [%0], %1;"
                         :: "l"(&g_hx[(t + 1) & 1][d]), "l"(pk) : "memory");
        } else if (l == 1) {
            __stcs(out + (size_t)t * DIM + d, hn);
        }
        // no trailing barrier: hsh/xpsh double-buffered
    }
}

// ---------------------------------------------------------------------------
extern "C" void kernel_launch(void* const* d_in, const int* in_sizes, int n_in,
                              void* d_out, int out_size)
{
    const float* xs = (const float*)d_in[0];   // [L, 512]
    const float* Wi = (const float*)d_in[1];   // [512, 2048]
    const float* Wh = (const float*)d_in[2];   // [512, 2048]
    const float* b  = (const float*)d_in[3];   // [2048]
    const float* c0 = (const float*)d_in[4];   // [512]
    const float* h0 = (const float*)d_in[5];   // [512]
    float* out = (float*)d_out;                // [L, 512]

    init_state<<<1, 512>>>(h0);
    lstm_fused<<<NCTA + GCTA, 512>>>(xs, Wi, b, Wh, c0, out);
}

// round 11
// speedup vs baseline: 1.2424x; 1.0540x over previous
#include <cuda_runtime.h>
#include <cstdint>
#include <cstddef>

#define L_SEQ 32768
#define DIM   512
#define DIM4  2048
#define NCTA  32          // recurrence CTAs (= 4 clusters of 8)
#define GCTA  96          // GEMM CTAs (12 clusters of 8); total grid = 128
#define NBLK  256         // row-blocks of 128 rows
#define NTIL  4096        // 256 row-blocks x 16 col-tiles
#define CLUSTER 8

// Scratch (static device globals: allocation-free per harness rules)
__device__ float g_xp[(size_t)L_SEQ * DIM4];      // 256 MB x-projection
__device__ unsigned long long g_hx[2][DIM];       // tagged hidden: (tag<<32)|bits
__device__ int g_cnt[NBLK];                       // per-row-block completed tiles

__device__ __forceinline__ uint32_t smem_u32(const void* p) {
    uint32_t a;
    asm("{ .reg .u64 t; cvta.to.shared.u64 t, %1; cvt.u32.u64 %0, t; }"
        : "=r"(a) : "l"(p));
    return a;
}

// ---------------------------------------------------------------------------
// Phase 0: reset global state each launch (graph-replay safe)
// ---------------------------------------------------------------------------
__global__ void init_state(const float* __restrict__ h0) {
    int tid = threadIdx.x;
    if (tid < NBLK) g_cnt[tid] = 0;
    if (tid < DIM) {
        g_hx[0][tid] = (unsigned long long)__float_as_uint(h0[tid]);  // tag 0
        g_hx[1][tid] = 0xFFFFFFFF00000000ull;                         // tag ~0
    }
}

struct GemmSmem { float As[16][132]; float Bs[16][128]; };   // 16.6 KB
struct RecSmem  {
    unsigned long long hloc[2][128];   // DSMEM-delivered tagged local h
    float hsh[2][DIM];
    float xpsh[2][64];
};

// ---------------------------------------------------------------------------
// Fused kernel, cluster (8,1,1). CTAs 0..31 (clusters 0-3): sequential LSTM
// with DSMEM broadcast of the intra-cluster h half + L2 tagged words for the
// inter-cluster half. CTAs 32..127: persistent x-projection GEMM.
// ---------------------------------------------------------------------------
__global__ __launch_bounds__(512, 1) void lstm_fused(
    const float* __restrict__ xs, const float* __restrict__ Wi,
    const float* __restrict__ bias, const float* __restrict__ Wh,
    const float* __restrict__ c0, const float* __restrict__ h0,
    float* __restrict__ out)
{
    __shared__ __align__(16) unsigned char s_raw[sizeof(GemmSmem)];
    const int tid = threadIdx.x;
    const int blk = blockIdx.x;

    // =================== GEMM path (CTAs 32..127) ===================
    if (blk >= NCTA) {
        GemmSmem& S = *reinterpret_cast<GemmSmem*>(s_raw);
        const int tx = tid & 31;
        const int ty = tid >> 5;

        for (int idx = blk - NCTA; idx < NTIL; idx += GCTA) {
            const int bm = (idx >> 4) * 128;   // row-major tile order
            const int bn = (idx & 15) * 128;

            float acc[8][4];
#pragma unroll
            for (int i = 0; i < 8; i++)
#pragma unroll
                for (int j = 0; j < 4; j++) acc[i][j] = 0.f;

            for (int k0 = 0; k0 < DIM; k0 += 16) {
                {   // A tile 128x16, transposed into As[k][m]
                    int row = tid >> 2;
                    int c4  = (tid & 3) << 2;
                    float4 v = *(const float4*)(xs + (size_t)(bm + row) * DIM + k0 + c4);
                    S.As[c4 + 0][row] = v.x;
                    S.As[c4 + 1][row] = v.y;
                    S.As[c4 + 2][row] = v.z;
                    S.As[c4 + 3][row] = v.w;
                }
                {   // B tile 16x128
                    int row = tid >> 5;
                    int c4  = (tid & 31) << 2;
                    *(float4*)(&S.Bs[row][c4]) =
                        *(const float4*)(Wi + (size_t)(k0 + row) * DIM4 + bn + c4);
                }
                __syncthreads();
#pragma unroll
                for (int kk = 0; kk < 16; kk++) {
                    float a[8], bb[4];
                    *(float4*)(a)     = *(const float4*)(&S.As[kk][ty * 8]);
                    *(float4*)(a + 4) = *(const float4*)(&S.As[kk][ty * 8 + 4]);
                    *(float4*)(bb)    = *(const float4*)(&S.Bs[kk][tx * 4]);
#pragma unroll
                    for (int i = 0; i < 8; i++)
#pragma unroll
                        for (int j = 0; j < 4; j++)
                            acc[i][j] = fmaf(a[i], bb[j], acc[i][j]);
                }
                __syncthreads();
            }

            float4 bv = *(const float4*)(bias + bn + tx * 4);
#pragma unroll
            for (int i = 0; i < 8; i++) {
                float4 o;
                o.x = acc[i][0] + bv.x;
                o.y = acc[i][1] + bv.y;
                o.z = acc[i][2] + bv.z;
                o.w = acc[i][3] + bv.w;
                *(float4*)(g_xp + (size_t)(bm + ty * 8 + i) * DIM4 + bn + tx * 4) = o;
            }
            __threadfence();
            __syncthreads();
            if (tid == 0) atomicAdd(&g_cnt[idx >> 4], 1);
        }
        return;
    }

    // =================== Recurrence path (CTAs 0..31) ===================
    RecSmem& R = *reinterpret_cast<RecSmem*>(s_raw);
    const int w  = tid >> 5;             // warp 0..15 -> local d
    const int l  = tid & 31;
    const int d  = blk * 16 + w;
    const int g  = l >> 3;               // lane-group -> gate (0:i 1:f 2:g 3:o)
    const int cb = (blk >> 3) * 128;     // this cluster's k/d base
    const int ls = (blk & 7) * 16 + w;   // own slot in cluster-local hloc

    // Register-resident weights, k rotated so m=0,1 are the LOCAL cluster half:
    // lane l covers k = (cb + 2l + 64m + j) mod 512
    float wreg[4][8][2];
#pragma unroll
    for (int q = 0; q < 4; q++)
#pragma unroll
        for (int m = 0; m < 8; m++) {
            int kb = (cb + 2 * l + 64 * m) & 511;
#pragma unroll
            for (int j = 0; j < 2; j++)
                wreg[q][m][j] = __ldg(Wh + (size_t)(kb + j) * DIM4 + q * DIM + d);
        }

    float cst = __ldg(c0 + d);

    const float escale = (g == 2) ? -2.0f : -1.0f;
    const float pa     = (g == 2) ?  2.0f :  1.0f;
    const float pb     = (g == 2) ? -1.0f :  0.0f;

    const float* xp_base = g_xp + (tid >> 4) * DIM + blk * 16 + (tid & 15);
    const unsigned FULL = 0xffffffffu;

    // Init local tagged buffer: buf0 <- {tag0, h0}, buf1 <- never-match
    if (tid < 128) {
        R.hloc[0][tid] = (unsigned long long)__float_as_uint(__ldg(h0 + cb + tid));
        R.hloc[1][tid] = 0xFFFFFFFF00000000ull;
    }
    __syncthreads();
    // Peers' hloc must be initialized before anyone's step-0 publish
    asm volatile("barrier.cluster.arrive.aligned;" ::: "memory");
    asm volatile("barrier.cluster.wait.aligned;"   ::: "memory");

    int rdy = 0;   // row-blocks confirmed complete (tid0 only)
    if (tid == 0) {
        while (rdy < 1) {
            int c;
            asm volatile("ld.acquire.gpu.global.b32 %0, [%1];"
                         : "=r"(c) : "l"(g_cnt + rdy));
            if (c == 16) rdy++;
        }
    }
    __syncthreads();

    float xv = (tid < 64) ? __ldcs(xp_base) : 0.f;

#define DO_MM(mm)                                                              \
    do {                                                                       \
        float2 hv = *(const float2*)(&R.hsh[pbuf][(cb + 2 * l + 64 * (mm)) & 511]); \
        s0 = fmaf(hv.x, wreg[0][mm][0], fmaf(hv.y, wreg[0][mm][1], s0));       \
        s1 = fmaf(hv.x, wreg[1][mm][0], fmaf(hv.y, wreg[1][mm][1], s1));       \
        s2 = fmaf(hv.x, wreg[2][mm][0], fmaf(hv.y, wreg[2][mm][1], s2));       \
        s3 = fmaf(hv.x, wreg[3][mm][0], fmaf(hv.y, wreg[3][mm][1], s3));       \
    } while (0)

    for (int t = 0; t < L_SEQ; t++) {
        const int pbuf = t & 1;
        const unsigned want = (unsigned)t;
        float s0 = 0.f, s1 = 0.f, s2 = 0.f, s3 = 0.f;

        if (tid < 128) {
            // ---- warps 0-3: local half via DSMEM-written smem ----
            if (tid < 64) R.xpsh[pbuf][tid] = xv;
            {
                uint32_t pa_ = smem_u32(&R.hloc[pbuf][tid]);
                unsigned long long v;
                do {
                    asm volatile("ld.relaxed.cluster.shared.b64 %0, [%1];"
                                 : "=l"(v) : "r"(pa_));
                } while ((unsigned)(v >> 32) != want);
                R.hsh[pbuf][cb + tid] = __uint_as_float((unsigned)v);
            }
            if (tid == 0) {   // GEMM row-block readiness for prefetch t+1
                int need = ((t + 1) >> 7) + 1;
                if (need > NBLK) need = NBLK;
                while (rdy < need) {
                    int c;
                    asm volatile("ld.acquire.gpu.global.b32 %0, [%1];"
                                 : "=r"(c) : "l"(g_cnt + rdy));
                    if (c == 16) rdy++;
                }
            }
            asm volatile("bar.sync 1, 128;" ::: "memory");
            if (tid < 64 && t + 1 < L_SEQ)
                xv = __ldcs(xp_base + (size_t)(t + 1) * DIM4);
            // Phase A (local half) overlaps the remote L2 flight
            DO_MM(0);
            DO_MM(1);
            asm volatile("bar.sync 2, 512;" ::: "memory");
        } else {
            // ---- warps 4-15: remote half via tagged L2 words ----
            const int rk = (cb + 128 + (tid - 128)) & 511;
            const unsigned long long* hp = &g_hx[pbuf][rk];
            unsigned long long va, vb, v;
            asm volatile("ld.relaxed.gpu.global.b64 %0, [%1];"
                         : "=l"(va) : "l"(hp));
            unsigned dly = tid | 1u;          // ~220cy opaque phase offset
#pragma unroll
            for (int i = 0; i < 48; i++)
                asm volatile("mad.lo.u32 %0, %0, 3, 1;" : "+r"(dly));
            unsigned zr = __shfl_sync(FULL, dly, l) ^ dly;   // == 0, opaque
            const unsigned long long* hpb =
                (const unsigned long long*)((const char*)hp + zr);
            asm volatile("ld.relaxed.gpu.global.b64 %0, [%1];"
                         : "=l"(vb) : "l"(hpb));
            for (;;) {
                if ((unsigned)(va >> 32) == want) { v = va; break; }
                asm volatile("ld.relaxed.gpu.global.b64 %0, [%1];"
                             : "=l"(va) : "l"(hp));
                if ((unsigned)(vb >> 32) == want) { v = vb; break; }
                asm volatile("ld.relaxed.gpu.global.b64 %0, [%1];"
                             : "=l"(vb) : "l"(hpb));
            }
            R.hsh[pbuf][rk] = __uint_as_float((unsigned)v);
            asm volatile("bar.sync 2, 512;" ::: "memory");
            DO_MM(0);
            DO_MM(1);
        }

        // Phase B: remote half (hsh complete after bar 2)
        DO_MM(2); DO_MM(3); DO_MM(4); DO_MM(5); DO_MM(6); DO_MM(7);

        // Merged butterfly reduce: 4 sums over 32 lanes, ~9 shfls;
        // lane-group g ends holding gate-g total.
        float t0 = __shfl_xor_sync(FULL, s0, 16);
        float t2 = __shfl_xor_sync(FULL, s2, 16);
        float av = (l < 16) ? (s0 + t0) : (s2 + t2);
        float t1 = __shfl_xor_sync(FULL, s1, 16);
        float t3 = __shfl_xor_sync(FULL, s3, 16);
        float bv = (l < 16) ? (s1 + t1) : (s3 + t3);
        float a8 = __shfl_xor_sync(FULL, av, 8);
        float b8 = __shfl_xor_sync(FULL, bv, 8);
        float cc = ((l & 8) == 0) ? (av + a8) : (bv + b8);
        cc += __shfl_xor_sync(FULL, cc, 4);
        cc += __shfl_xor_sync(FULL, cc, 2);
        cc += __shfl_xor_sync(FULL, cc, 1);

        // Activation (branchless per lane-group)
        float y   = cc + R.xpsh[pbuf][g * 16 + w];
        float e   = __expf(escale * y);
        float r   = __fdividef(1.0f, 1.0f + e);
        float act = fmaf(pa, r, pb);   // sigmoid(y) or tanh(y)

        float vi = __shfl_sync(FULL, act, 0);
        float vf = __shfl_sync(FULL, act, 8);
        float vg = __shfl_sync(FULL, act, 16);
        float vo = __shfl_sync(FULL, act, 24);

        cst = fmaf(vf, cst, vi * vg);
        float ca = fminf(fmaxf(cst, -40.f), 40.f);
        float e2 = __expf(-2.0f * ca);
        float th = fmaf(2.0f, __fdividef(1.0f, 1.0f + e2), -1.0f);
        float hn = vo * th;

        if (l == 0) {
            unsigned long long pk =
                ((unsigned long long)(unsigned)(t + 1) << 32) |
                (unsigned long long)__float_as_uint(hn);
            // L2 word first (longest flight), then 8 DSMEM peer copies
            asm volatile("st.relaxed.gpu.global.b64 [%0], %1;"
                         :: "l"(&g_hx[(t + 1) & 1][d]), "l"(pk) : "memory");
            uint32_t laddr = smem_u32(&R.hloc[(t + 1) & 1][ls]);
#pragma unroll
            for (int rr = 0; rr < CLUSTER; rr++) {
                uint32_t rem;
                asm("mapa.shared::cluster.u32 %0, %1, %2;"
                    : "=r"(rem) : "r"(laddr), "r"(rr));
                asm volatile("st.relaxed.cluster.shared::cluster.b64 [%0], %1;"
                             :: "r"(rem), "l"(pk) : "memory");
            }
        } else if (l == 1) {
            __stcs(out + (size_t)t * DIM + d, hn);
        }
        // no trailing barrier: hloc/hsh/xpsh all double-buffered
    }
#undef DO_MM
}

// ---------------------------------------------------------------------------
extern "C" void kernel_launch(void* const* d_in, const int* in_sizes, int n_in,
                              void* d_out, int out_size)
{
    const float* xs = (const float*)d_in[0];   // [L, 512]
    const float* Wi = (const float*)d_in[1];   // [512, 2048]
    const float* Wh = (const float*)d_in[2];   // [512, 2048]
    const float* b  = (const float*)d_in[3];   // [2048]
    const float* c0 = (const float*)d_in[4];   // [512]
    const float* h0 = (const float*)d_in[5];   // [512]
    float* out = (float*)d_out;                // [L, 512]

    init_state<<<1, 512>>>(h0);

    cudaLaunchConfig_t cfg = {};
    cfg.gridDim  = dim3(NCTA + GCTA, 1, 1);
    cfg.blockDim = dim3(512, 1, 1);
    cudaLaunchAttribute attr[1];
    attr[0].id = cudaLaunchAttributeClusterDimension;
    attr[0].val.clusterDim.x = CLUSTER;
    attr[0].val.clusterDim.y = 1;
    attr[0].val.clusterDim.z = 1;
    cfg.attrs = attr;
    cfg.numAttrs = 1;
    cudaLaunchKernelEx(&cfg, lstm_fused, xs, Wi, b, Wh, c0, h0, out);
}